// round 1
// baseline (speedup 1.0000x reference)
#include <cuda_runtime.h>
#include <math.h>

// Problem constants
#define B_SZ   4
#define L_SZ   5
#define NIMG   20          // B*L
#define CH     64
#define IMH    256
#define IMW    128
#define HW     (IMH*IMW)   // 32768

// ---------------- scratch (static device globals; no allocation) ----------------
__device__ float g_neigh[NIMG * CH * HW];          // (20,64,256,128)  167.8 MB
__device__ float g_c1[NIMG * 32 * 128 * 64];       // (20,32,128,64)
__device__ float g_c2[NIMG * 64 * 64 * 32];        // (20,64,64,32)
__device__ float g_c3[NIMG * 64 * 32 * 16];        // (20,64,32,16)
__device__ float g_attn[B_SZ * L_SZ];              // (4,5)

// ---------------- Kernel 1: affine grid + bilinear sample ----------------
// grid: (IMH, NIMG), block: IMW threads. Each thread = one (n,y,x), loops channels.
__global__ void sample_kernel(const float* __restrict__ x, const float* __restrict__ nam)
{
    const int n  = blockIdx.y;
    const int yy = blockIdx.x;
    const int xx = threadIdx.x;
    const int b  = n / L_SZ, l = n % L_SZ;

    // nam shape (4,5,5,2,3); tmats = nam[:,0] -> theta = nam[b][0][l]
    const float* th = nam + (b * 25 + l) * 6;
    const float t00 = th[0], t01 = th[1], t02 = th[2];
    const float t10 = th[3], t11 = th[4], t12 = th[5];

    const float gxn = (xx + 0.5f) * (2.0f / IMW) - 1.0f;
    const float gyn = (yy + 0.5f) * (2.0f / IMH) - 1.0f;
    const float gx = t00 * gxn + t01 * gyn + t02;
    const float gy = t10 * gxn + t11 * gyn + t12;
    const float sx = ((gx + 1.0f) * IMW - 1.0f) * 0.5f;
    const float sy = ((gy + 1.0f) * IMH - 1.0f) * 0.5f;

    const float x0f = floorf(sx), y0f = floorf(sy);
    const float fx = sx - x0f, fy = sy - y0f;
    const int x0 = (int)x0f, y0 = (int)y0f;

    const int   xs[2] = { x0, x0 + 1 };
    const int   ys[2] = { y0, y0 + 1 };
    const float wx[2] = { 1.0f - fx, fx };
    const float wy[2] = { 1.0f - fy, fy };

    int   off[4];
    float wv[4];
    int k = 0;
    #pragma unroll
    for (int jy = 0; jy < 2; jy++)
        #pragma unroll
        for (int jx = 0; jx < 2; jx++, k++) {
            const int ix = xs[jx], iy = ys[jy];
            const bool v = (ix >= 0) && (ix < IMW) && (iy >= 0) && (iy < IMH);
            const int icx = min(max(ix, 0), IMW - 1);
            const int icy = min(max(iy, 0), IMH - 1);
            off[k] = icy * IMW + icx;
            wv[k]  = v ? wx[jx] * wy[jy] : 0.0f;
        }

    const float* img = x + (size_t)n * CH * HW;
    float* dst = g_neigh + (size_t)n * CH * HW + yy * IMW + xx;
    #pragma unroll 4
    for (int c = 0; c < CH; c++) {
        const float* ic = img + (size_t)c * HW;
        const float v = wv[0] * ic[off[0]] + wv[1] * ic[off[1]]
                      + wv[2] * ic[off[2]] + wv[3] * ic[off[3]];
        dst[(size_t)c * HW] = v;
    }
}

// ---------------- Kernel 2-4: 4x4 stride-2 pad-1 conv + bias + relu ----------------
// Block computes 2 output rows x OW cols x all COUT channels of one image.
// Per-thread micro-tile: PC cout x 4 consecutive ox.
template<int CIN, int COUT, int IH, int IW>
__global__ void conv4x4s2(const float* __restrict__ in, const float* __restrict__ wgt,
                          const float* __restrict__ bias, float* __restrict__ out)
{
    constexpr int OH  = IH / 2, OW = IW / 2;
    constexpr int WP  = IW + 2;           // input cols incl. pad (x = -1..IW)
    constexpr int CCH = 8;                // cin chunk
    constexpr int PG  = OW / 2;           // position groups = 2 rows * (OW/4)
    constexpr int CG  = 256 / PG;         // cout groups
    constexpr int PC  = COUT / CG;        // cout per thread
    static_assert(PG * CG == 256 && CG * PC == COUT, "tiling");

    __shared__ float s_in[CCH][6][WP];
    __shared__ float s_w[CCH][COUT][16];

    const int n  = blockIdx.y;
    const int bx = blockIdx.x;            // output row-pair index
    const int t  = threadIdx.x;

    const int pg  = t % PG;
    const int cg  = t / PG;
    const int r   = pg / (OW / 4);        // 0..1 output row within pair
    const int ox0 = (pg % (OW / 4)) * 4;
    const int c0  = cg * PC;

    float acc[PC][4];
    #pragma unroll
    for (int cc = 0; cc < PC; cc++)
        #pragma unroll
        for (int p = 0; p < 4; p++) acc[cc][p] = 0.0f;

    const float* inN = in + (size_t)n * CIN * IH * IW;
    const int y0 = 4 * bx - 1;            // first input row needed

    for (int cb = 0; cb < CIN; cb += CCH) {
        __syncthreads();
        // cooperative load: input tile (6 rows x WP cols x CCH cins), zero-padded
        for (int idx = t; idx < CCH * 6 * WP; idx += 256) {
            const int ci  = idx / (6 * WP);
            const int rem = idx % (6 * WP);
            const int row = rem / WP, col = rem % WP;
            const int gy = y0 + row, gxp = col - 1;
            float v = 0.0f;
            if (gy >= 0 && gy < IH && gxp >= 0 && gxp < IW)
                v = inN[(size_t)(cb + ci) * IH * IW + (size_t)gy * IW + gxp];
            s_in[ci][row][col] = v;
        }
        // cooperative load: weights for this cin chunk
        for (int idx = t; idx < CCH * COUT * 16; idx += 256) {
            const int ci  = idx / (COUT * 16);
            const int rem = idx % (COUT * 16);
            const int o = rem / 16, k = rem % 16;
            s_w[ci][o][k] = wgt[(size_t)o * CIN * 16 + (size_t)(cb + ci) * 16 + k];
        }
        __syncthreads();

        for (int ci = 0; ci < CCH; ci++) {
            float a[4][10];
            #pragma unroll
            for (int j = 0; j < 4; j++)
                #pragma unroll
                for (int m = 0; m < 10; m++)
                    a[j][m] = s_in[ci][2 * r + j][2 * ox0 + m];

            #pragma unroll
            for (int cc = 0; cc < PC; cc++) {
                float w[16];
                #pragma unroll
                for (int k2 = 0; k2 < 16; k2++) w[k2] = s_w[ci][c0 + cc][k2];
                #pragma unroll
                for (int p = 0; p < 4; p++) {
                    float s = acc[cc][p];
                    #pragma unroll
                    for (int ky = 0; ky < 4; ky++)
                        #pragma unroll
                        for (int kx = 0; kx < 4; kx++)
                            s = fmaf(a[ky][2 * p + kx], w[ky * 4 + kx], s);
                    acc[cc][p] = s;
                }
            }
        }
    }

    const int oy = 2 * bx + r;
    #pragma unroll
    for (int cc = 0; cc < PC; cc++) {
        const float bv = bias[c0 + cc];
        #pragma unroll
        for (int p = 0; p < 4; p++) {
            const float v = acc[cc][p] + bv;
            out[(((size_t)n * COUT + (c0 + cc)) * OH + oy) * OW + ox0 + p] = fmaxf(v, 0.0f);
        }
    }
}

// ---------------- Kernel 5: pool + key/query MLPs + attention softmax ----------------
// One block per batch b (B=4), 256 threads. All operands tiny; smem staging.
__global__ void attn_kernel(const float* __restrict__ kf1w, const float* __restrict__ kf1b,
                            const float* __restrict__ kf2w, const float* __restrict__ kf2b,
                            const float* __restrict__ kf3w, const float* __restrict__ kf3b,
                            const float* __restrict__ qf1w, const float* __restrict__ qf1b,
                            const float* __restrict__ qf2w, const float* __restrict__ qf2b,
                            const float* __restrict__ qf3w, const float* __restrict__ qf3b,
                            const float* __restrict__ aw,   const float* __restrict__ ab)
{
    const int b = blockIdx.x;
    const int t = threadIdx.x;

    __shared__ float pooled[L_SZ][64];
    __shared__ float h1[L_SZ][256];
    __shared__ float h2[L_SZ][128];
    __shared__ float keys[L_SZ][256];
    __shared__ float q1[256], q2[128], qv[32], qq[256];
    __shared__ float logit[L_SZ];

    // mean pool conv3 output: (l, c) over 32*16 = 512 spatial
    for (int idx = t; idx < L_SZ * 64; idx += 256) {
        const int l = idx / 64, c = idx % 64;
        const float* p = g_c3 + ((size_t)(b * L_SZ + l) * 64 + c) * 512;
        float s = 0.0f;
        for (int i = 0; i < 512; i++) s += p[i];
        pooled[l][c] = s * (1.0f / 512.0f);
    }
    __syncthreads();

    // keys fc1: 64 -> 256, relu
    for (int idx = t; idx < L_SZ * 256; idx += 256) {
        const int l = idx / 256, o = idx % 256;
        float s = kf1b[o];
        for (int i = 0; i < 64; i++) s = fmaf(pooled[l][i], kf1w[o * 64 + i], s);
        h1[l][o] = fmaxf(s, 0.0f);
    }
    __syncthreads();
    // keys fc2: 256 -> 128, relu
    for (int idx = t; idx < L_SZ * 128; idx += 256) {
        const int l = idx / 128, o = idx % 128;
        float s = kf2b[o];
        for (int i = 0; i < 256; i++) s = fmaf(h1[l][i], kf2w[o * 256 + i], s);
        h2[l][o] = fmaxf(s, 0.0f);
    }
    __syncthreads();
    // keys fc3: 128 -> 256
    for (int idx = t; idx < L_SZ * 256; idx += 256) {
        const int l = idx / 256, o = idx % 256;
        float s = kf3b[o];
        for (int i = 0; i < 128; i++) s = fmaf(h2[l][i], kf3w[o * 128 + i], s);
        keys[l][o] = s;
    }
    __syncthreads();

    // query path from pooled[0]
    {
        float s = qf1b[t];
        for (int i = 0; i < 64; i++) s = fmaf(pooled[0][i], qf1w[t * 64 + i], s);
        q1[t] = fmaxf(s, 0.0f);
    }
    __syncthreads();
    if (t < 128) {
        float s = qf2b[t];
        for (int i = 0; i < 256; i++) s = fmaf(q1[i], qf2w[t * 256 + i], s);
        q2[t] = fmaxf(s, 0.0f);
    }
    __syncthreads();
    if (t < 32) {
        float s = qf3b[t];
        for (int i = 0; i < 128; i++) s = fmaf(q2[i], qf3w[t * 128 + i], s);
        qv[t] = s;
    }
    __syncthreads();
    // q = qry @ attn_w.T + attn_b : (32) -> (256)
    {
        float s = ab[t];
        for (int i = 0; i < 32; i++) s = fmaf(qv[i], aw[t * 32 + i], s);
        qq[t] = s;
    }
    __syncthreads();
    if (t < L_SZ) {
        float s = 0.0f;
        for (int i = 0; i < 256; i++) s = fmaf(keys[t][i], qq[i], s);
        logit[t] = s;
    }
    __syncthreads();
    if (t == 0) {
        float m = logit[0];
        for (int l = 1; l < L_SZ; l++) m = fmaxf(m, logit[l]);
        float e[L_SZ], ssum = 0.0f;
        for (int l = 0; l < L_SZ; l++) { e[l] = expf(logit[l] - m); ssum += e[l]; }
        const float inv = 1.0f / ssum;
        for (int l = 0; l < L_SZ; l++) g_attn[b * L_SZ + l] = e[l] * inv;
    }
}

// ---------------- Kernel 6: attention-weighted sum of neigh ----------------
__global__ void fuse_kernel(float* __restrict__ out)
{
    const size_t i = (size_t)blockIdx.x * blockDim.x + threadIdx.x;
    const size_t per_b = (size_t)CH * HW / 4;     // float4 per batch image
    const int b = (int)(i / per_b);
    const size_t rem = i % per_b;

    float a[L_SZ];
    #pragma unroll
    for (int l = 0; l < L_SZ; l++) a[l] = g_attn[b * L_SZ + l];

    const float4* nv = (const float4*)g_neigh;
    float4 s = make_float4(0.f, 0.f, 0.f, 0.f);
    #pragma unroll
    for (int l = 0; l < L_SZ; l++) {
        const float4 v = nv[(size_t)(b * L_SZ + l) * per_b + rem];
        s.x = fmaf(a[l], v.x, s.x);
        s.y = fmaf(a[l], v.y, s.y);
        s.z = fmaf(a[l], v.z, s.z);
        s.w = fmaf(a[l], v.w, s.w);
    }
    ((float4*)out)[i] = s;
}

// ---------------- launch ----------------
extern "C" void kernel_launch(void* const* d_in, const int* in_sizes, int n_in,
                              void* d_out, int out_size)
{
    const float* x    = (const float*)d_in[0];
    const float* nam  = (const float*)d_in[2];
    const float* w1   = (const float*)d_in[3];
    const float* b1   = (const float*)d_in[4];
    const float* w2   = (const float*)d_in[5];
    const float* b2   = (const float*)d_in[6];
    const float* w3   = (const float*)d_in[7];
    const float* b3   = (const float*)d_in[8];
    const float* kf1w = (const float*)d_in[9];
    const float* kf1b = (const float*)d_in[10];
    const float* kf2w = (const float*)d_in[11];
    const float* kf2b = (const float*)d_in[12];
    const float* kf3w = (const float*)d_in[13];
    const float* kf3b = (const float*)d_in[14];
    const float* qf1w = (const float*)d_in[15];
    const float* qf1b = (const float*)d_in[16];
    const float* qf2w = (const float*)d_in[17];
    const float* qf2b = (const float*)d_in[18];
    const float* qf3w = (const float*)d_in[19];
    const float* qf3b = (const float*)d_in[20];
    const float* aw   = (const float*)d_in[21];
    const float* ab   = (const float*)d_in[22];

    float *p_neigh, *p_c1, *p_c2, *p_c3;
    cudaGetSymbolAddress((void**)&p_neigh, g_neigh);
    cudaGetSymbolAddress((void**)&p_c1, g_c1);
    cudaGetSymbolAddress((void**)&p_c2, g_c2);
    cudaGetSymbolAddress((void**)&p_c3, g_c3);

    sample_kernel<<<dim3(IMH, NIMG), IMW>>>(x, nam);
    conv4x4s2<64, 32, 256, 128><<<dim3(64, NIMG), 256>>>(p_neigh, w1, b1, p_c1);
    conv4x4s2<32, 64, 128,  64><<<dim3(32, NIMG), 256>>>(p_c1, w2, b2, p_c2);
    conv4x4s2<64, 64,  64,  32><<<dim3(16, NIMG), 256>>>(p_c2, w3, b3, p_c3);
    attn_kernel<<<B_SZ, 256>>>(kf1w, kf1b, kf2w, kf2b, kf3w, kf3b,
                               qf1w, qf1b, qf2w, qf2b, qf3w, qf3b, aw, ab);
    const size_t n4 = (size_t)B_SZ * CH * HW / 4;   // 2,097,152 float4
    fuse_kernel<<<(unsigned)(n4 / 256), 256>>>((float*)d_out);
}

// round 2
// speedup vs baseline: 1.5265x; 1.5265x over previous
#include <cuda_runtime.h>
#include <math.h>

// Problem constants
#define B_SZ   4
#define L_SZ   5
#define NIMG   20          // B*L
#define CH     64
#define IMH    256
#define IMW    128
#define HW     (IMH*IMW)   // 32768

// ---------------- scratch (static device globals; no allocation) ----------------
__device__ float g_neigh[NIMG * CH * HW];          // (20,64,256,128)
__device__ float g_c1[NIMG * 32 * 128 * 64];       // (20,32,128,64)
__device__ float g_c2[NIMG * 64 * 64 * 32];        // (20,64,64,32)
__device__ float g_c3[NIMG * 64 * 32 * 16];        // (20,64,32,16)
__device__ float g_attn[B_SZ * L_SZ];              // (4,5)

// ---------------- Kernel 1: affine grid + bilinear sample ----------------
__global__ void sample_kernel(const float* __restrict__ x, const float* __restrict__ nam)
{
    const int n  = blockIdx.y;
    const int yy = blockIdx.x;
    const int xx = threadIdx.x;
    const int b  = n / L_SZ, l = n % L_SZ;

    const float* th = nam + (b * 25 + l) * 6;
    const float t00 = th[0], t01 = th[1], t02 = th[2];
    const float t10 = th[3], t11 = th[4], t12 = th[5];

    const float gxn = (xx + 0.5f) * (2.0f / IMW) - 1.0f;
    const float gyn = (yy + 0.5f) * (2.0f / IMH) - 1.0f;
    const float gx = t00 * gxn + t01 * gyn + t02;
    const float gy = t10 * gxn + t11 * gyn + t12;
    const float sx = ((gx + 1.0f) * IMW - 1.0f) * 0.5f;
    const float sy = ((gy + 1.0f) * IMH - 1.0f) * 0.5f;

    const float x0f = floorf(sx), y0f = floorf(sy);
    const float fx = sx - x0f, fy = sy - y0f;
    const int x0 = (int)x0f, y0 = (int)y0f;

    const int   xs[2] = { x0, x0 + 1 };
    const int   ys[2] = { y0, y0 + 1 };
    const float wx[2] = { 1.0f - fx, fx };
    const float wy[2] = { 1.0f - fy, fy };

    int   off[4];
    float wv[4];
    int k = 0;
    #pragma unroll
    for (int jy = 0; jy < 2; jy++)
        #pragma unroll
        for (int jx = 0; jx < 2; jx++, k++) {
            const int ix = xs[jx], iy = ys[jy];
            const bool v = (ix >= 0) && (ix < IMW) && (iy >= 0) && (iy < IMH);
            const int icx = min(max(ix, 0), IMW - 1);
            const int icy = min(max(iy, 0), IMH - 1);
            off[k] = icy * IMW + icx;
            wv[k]  = v ? wx[jx] * wy[jy] : 0.0f;
        }

    const float* img = x + (size_t)n * CH * HW;
    float* dst = g_neigh + (size_t)n * CH * HW + yy * IMW + xx;
    #pragma unroll 4
    for (int c = 0; c < CH; c++) {
        const float* ic = img + (size_t)c * HW;
        const float v = wv[0] * ic[off[0]] + wv[1] * ic[off[1]]
                      + wv[2] * ic[off[2]] + wv[3] * ic[off[3]];
        dst[(size_t)c * HW] = v;
    }
}

// ---------------- 4x4 stride-2 pad-1 conv + bias + relu (v2) ----------------
// Block: 256 threads, computes 2 output rows x OW cols x COUTB couts of one image.
// Per-thread: PC couts x OXT consecutive ox. Register-resident activation/weight
// micro-tiles via vectorized LDS. blockIdx.z splits cout into COUT/COUTB groups.
template<int CIN, int COUT, int IH, int IW, int COUTB, int OXT>
__global__ __launch_bounds__(256, 2)
void conv4x4s2_v2(const float* __restrict__ in, const float* __restrict__ wgt,
                  const float* __restrict__ bias, float* __restrict__ out)
{
    constexpr int OH   = IH / 2, OW = IW / 2;
    constexpr int WP   = IW + 2;                    // valid cols incl. 1-pad each side
    constexpr int WPAD = (WP + 3) & ~3;             // float4-aligned pitch
    constexpr int CCH  = 8;                         // cin chunk
    constexpr int G    = OW / OXT;                  // ox groups per row
    constexpr int PG   = 2 * G;                     // position groups (2 rows)
    constexpr int CG   = 256 / PG;                  // cout groups among threads
    constexpr int PC   = COUTB / CG;                // couts per thread
    constexpr int AW   = 2 * OXT + 2;               // activation cols per row
    static_assert(PG * CG == 256 && CG * PC == COUTB, "tiling");

    __shared__ float s_in[CCH][6][WPAD];
    __shared__ float s_w[CCH][COUTB][16];

    const int n  = blockIdx.y;
    const int bx = blockIdx.x;                      // output row-pair
    const int cz = blockIdx.z;                      // cout group
    const int t  = threadIdx.x;

    const int pg  = t % PG;
    const int cg  = t / PG;
    const int r   = pg / G;                         // 0..1
    const int ox0 = (pg % G) * OXT;
    const int c0  = cg * PC;
    const int cbase = cz * COUTB;

    float acc[PC][OXT];
    #pragma unroll
    for (int cc = 0; cc < PC; cc++)
        #pragma unroll
        for (int p = 0; p < OXT; p++) acc[cc][p] = 0.0f;

    const float* inN = in + (size_t)n * CIN * IH * IW;
    const int y0 = 4 * bx - 1;

    for (int cb = 0; cb < CIN; cb += CCH) {
        // ---- cooperative loads ----
        for (int idx = t; idx < CCH * 6 * WPAD; idx += 256) {
            const int ci  = idx / (6 * WPAD);
            const int rem = idx % (6 * WPAD);
            const int row = rem / WPAD, col = rem % WPAD;
            const int gy = y0 + row, gxp = col - 1;
            float v = 0.0f;
            if (col < WP && gy >= 0 && gy < IH && gxp >= 0 && gxp < IW)
                v = inN[(size_t)(cb + ci) * IH * IW + (size_t)gy * IW + gxp];
            s_in[ci][row][col] = v;
        }
        for (int idx = t; idx < CCH * COUTB * 16; idx += 256) {
            const int ci  = idx / (COUTB * 16);
            const int rem = idx % (COUTB * 16);
            const int o = rem / 16, k = rem % 16;
            s_w[ci][o][k] = wgt[(size_t)(cbase + o) * CIN * 16 + (size_t)(cb + ci) * 16 + k];
        }
        __syncthreads();

        #pragma unroll
        for (int ci = 0; ci < CCH; ci++) {
            // activation micro-tile: 4 rows x AW cols, vectorized LDS
            float a[4][AW];
            #pragma unroll
            for (int j = 0; j < 4; j++) {
                const float* rp = &s_in[ci][2 * r + j][2 * ox0];   // 16B-aligned
                const float4 v0 = *(const float4*)rp;
                a[j][0] = v0.x; a[j][1] = v0.y; a[j][2] = v0.z; a[j][3] = v0.w;
                if (OXT == 4) {
                    const float4 v1 = *(const float4*)(rp + 4);
                    a[j][4] = v1.x; a[j][5] = v1.y; a[j][6] = v1.z; a[j][7] = v1.w;
                    const float2 v2 = *(const float2*)(rp + 8);
                    a[j][8] = v2.x; a[j][9] = v2.y;
                } else {
                    const float2 v1 = *(const float2*)(rp + 4);
                    a[j][4] = v1.x; a[j][5] = v1.y;
                }
            }
            #pragma unroll
            for (int cc = 0; cc < PC; cc++) {
                const float* wp = &s_w[ci][c0 + cc][0];            // broadcast
                float w[16];
                #pragma unroll
                for (int q = 0; q < 4; q++) {
                    const float4 wv = *(const float4*)(wp + 4 * q);
                    w[4*q] = wv.x; w[4*q+1] = wv.y; w[4*q+2] = wv.z; w[4*q+3] = wv.w;
                }
                #pragma unroll
                for (int p = 0; p < OXT; p++) {
                    float s = acc[cc][p];
                    #pragma unroll
                    for (int ky = 0; ky < 4; ky++)
                        #pragma unroll
                        for (int kx = 0; kx < 4; kx++)
                            s = fmaf(a[ky][2 * p + kx], w[ky * 4 + kx], s);
                    acc[cc][p] = s;
                }
            }
        }
        __syncthreads();
    }

    const int oy = 2 * bx + r;
    #pragma unroll
    for (int cc = 0; cc < PC; cc++) {
        const float bv = bias[cbase + c0 + cc];
        float* op = out + (((size_t)n * COUT + (cbase + c0 + cc)) * OH + oy) * OW + ox0;
        if (OXT == 4) {
            float4 o4;
            o4.x = fmaxf(acc[cc][0] + bv, 0.0f);
            o4.y = fmaxf(acc[cc][1] + bv, 0.0f);
            o4.z = fmaxf(acc[cc][2] + bv, 0.0f);
            o4.w = fmaxf(acc[cc][3] + bv, 0.0f);
            *(float4*)op = o4;
        } else {
            float2 o2;
            o2.x = fmaxf(acc[cc][0] + bv, 0.0f);
            o2.y = fmaxf(acc[cc][1] + bv, 0.0f);
            *(float2*)op = o2;
        }
    }
}

// ---------------- Kernel 5: pool + key/query MLPs + attention softmax ----------------
__global__ void attn_kernel(const float* __restrict__ kf1w, const float* __restrict__ kf1b,
                            const float* __restrict__ kf2w, const float* __restrict__ kf2b,
                            const float* __restrict__ kf3w, const float* __restrict__ kf3b,
                            const float* __restrict__ qf1w, const float* __restrict__ qf1b,
                            const float* __restrict__ qf2w, const float* __restrict__ qf2b,
                            const float* __restrict__ qf3w, const float* __restrict__ qf3b,
                            const float* __restrict__ aw,   const float* __restrict__ ab)
{
    const int b = blockIdx.x;
    const int t = threadIdx.x;

    __shared__ float pooled[L_SZ][64];
    __shared__ float h1[L_SZ][256];
    __shared__ float h2[L_SZ][128];
    __shared__ float keys[L_SZ][256];
    __shared__ float q1[256], q2[128], qv[32], qq[256];
    __shared__ float logit[L_SZ];

    // mean pool conv3 output: (l, c) over 512 spatial, float4-vectorized
    for (int idx = t; idx < L_SZ * 64; idx += 256) {
        const int l = idx / 64, c = idx % 64;
        const float4* p = (const float4*)(g_c3 + ((size_t)(b * L_SZ + l) * 64 + c) * 512);
        float s = 0.0f;
        #pragma unroll 4
        for (int i = 0; i < 128; i++) {
            const float4 v = p[i];
            s += (v.x + v.y) + (v.z + v.w);
        }
        pooled[l][c] = s * (1.0f / 512.0f);
    }
    __syncthreads();

    for (int idx = t; idx < L_SZ * 256; idx += 256) {
        const int l = idx / 256, o = idx % 256;
        float s = kf1b[o];
        for (int i = 0; i < 64; i++) s = fmaf(pooled[l][i], kf1w[o * 64 + i], s);
        h1[l][o] = fmaxf(s, 0.0f);
    }
    __syncthreads();
    for (int idx = t; idx < L_SZ * 128; idx += 256) {
        const int l = idx / 128, o = idx % 128;
        float s = kf2b[o];
        for (int i = 0; i < 256; i++) s = fmaf(h1[l][i], kf2w[o * 256 + i], s);
        h2[l][o] = fmaxf(s, 0.0f);
    }
    __syncthreads();
    for (int idx = t; idx < L_SZ * 256; idx += 256) {
        const int l = idx / 256, o = idx % 256;
        float s = kf3b[o];
        for (int i = 0; i < 128; i++) s = fmaf(h2[l][i], kf3w[o * 128 + i], s);
        keys[l][o] = s;
    }
    __syncthreads();

    {
        float s = qf1b[t];
        for (int i = 0; i < 64; i++) s = fmaf(pooled[0][i], qf1w[t * 64 + i], s);
        q1[t] = fmaxf(s, 0.0f);
    }
    __syncthreads();
    if (t < 128) {
        float s = qf2b[t];
        for (int i = 0; i < 256; i++) s = fmaf(q1[i], qf2w[t * 256 + i], s);
        q2[t] = fmaxf(s, 0.0f);
    }
    __syncthreads();
    if (t < 32) {
        float s = qf3b[t];
        for (int i = 0; i < 128; i++) s = fmaf(q2[i], qf3w[t * 128 + i], s);
        qv[t] = s;
    }
    __syncthreads();
    {
        float s = ab[t];
        for (int i = 0; i < 32; i++) s = fmaf(qv[i], aw[t * 32 + i], s);
        qq[t] = s;
    }
    __syncthreads();
    if (t < L_SZ) {
        float s = 0.0f;
        for (int i = 0; i < 256; i++) s = fmaf(keys[t][i], qq[i], s);
        logit[t] = s;
    }
    __syncthreads();
    if (t == 0) {
        float m = logit[0];
        for (int l = 1; l < L_SZ; l++) m = fmaxf(m, logit[l]);
        float e[L_SZ], ssum = 0.0f;
        for (int l = 0; l < L_SZ; l++) { e[l] = expf(logit[l] - m); ssum += e[l]; }
        const float inv = 1.0f / ssum;
        for (int l = 0; l < L_SZ; l++) g_attn[b * L_SZ + l] = e[l] * inv;
    }
}

// ---------------- Kernel 6: attention-weighted sum of neigh ----------------
__global__ void fuse_kernel(float* __restrict__ out)
{
    const size_t i = (size_t)blockIdx.x * blockDim.x + threadIdx.x;
    const size_t per_b = (size_t)CH * HW / 4;
    const int b = (int)(i / per_b);
    const size_t rem = i % per_b;

    float a[L_SZ];
    #pragma unroll
    for (int l = 0; l < L_SZ; l++) a[l] = g_attn[b * L_SZ + l];

    const float4* nv = (const float4*)g_neigh;
    float4 s = make_float4(0.f, 0.f, 0.f, 0.f);
    #pragma unroll
    for (int l = 0; l < L_SZ; l++) {
        const float4 v = nv[(size_t)(b * L_SZ + l) * per_b + rem];
        s.x = fmaf(a[l], v.x, s.x);
        s.y = fmaf(a[l], v.y, s.y);
        s.z = fmaf(a[l], v.z, s.z);
        s.w = fmaf(a[l], v.w, s.w);
    }
    ((float4*)out)[i] = s;
}

// ---------------- launch ----------------
extern "C" void kernel_launch(void* const* d_in, const int* in_sizes, int n_in,
                              void* d_out, int out_size)
{
    const float* x    = (const float*)d_in[0];
    const float* nam  = (const float*)d_in[2];
    const float* w1   = (const float*)d_in[3];
    const float* b1   = (const float*)d_in[4];
    const float* w2   = (const float*)d_in[5];
    const float* b2   = (const float*)d_in[6];
    const float* w3   = (const float*)d_in[7];
    const float* b3   = (const float*)d_in[8];
    const float* kf1w = (const float*)d_in[9];
    const float* kf1b = (const float*)d_in[10];
    const float* kf2w = (const float*)d_in[11];
    const float* kf2b = (const float*)d_in[12];
    const float* kf3w = (const float*)d_in[13];
    const float* kf3b = (const float*)d_in[14];
    const float* qf1w = (const float*)d_in[15];
    const float* qf1b = (const float*)d_in[16];
    const float* qf2w = (const float*)d_in[17];
    const float* qf2b = (const float*)d_in[18];
    const float* qf3w = (const float*)d_in[19];
    const float* qf3b = (const float*)d_in[20];
    const float* aw   = (const float*)d_in[21];
    const float* ab   = (const float*)d_in[22];

    float *p_neigh, *p_c1, *p_c2, *p_c3;
    cudaGetSymbolAddress((void**)&p_neigh, g_neigh);
    cudaGetSymbolAddress((void**)&p_c1, g_c1);
    cudaGetSymbolAddress((void**)&p_c2, g_c2);
    cudaGetSymbolAddress((void**)&p_c3, g_c3);

    sample_kernel<<<dim3(IMH, NIMG), IMW>>>(x, nam);

    // conv1: 64->32 on 256x128. COUTB=32, OXT=4 -> PG=32,CG=8,PC=4. grid 64x20x1.
    conv4x4s2_v2<64, 32, 256, 128, 32, 4><<<dim3(64, NIMG, 1), 256>>>(p_neigh, w1, b1, p_c1);
    // conv2: 32->64 on 128x64. COUTB=32, OXT=4 -> PG=16,CG=16,PC=2. grid 32x20x2.
    conv4x4s2_v2<32, 64, 128, 64, 32, 4><<<dim3(32, NIMG, 2), 256>>>(p_c1, w2, b2, p_c2);
    // conv3: 64->64 on 64x32. COUTB=16, OXT=2 -> PG=16,CG=16,PC=1. grid 16x20x4.
    conv4x4s2_v2<64, 64, 64, 32, 16, 2><<<dim3(16, NIMG, 4), 256>>>(p_c2, w3, b3, p_c3);

    attn_kernel<<<B_SZ, 256>>>(kf1w, kf1b, kf2w, kf2b, kf3w, kf3b,
                               qf1w, qf1b, qf2w, qf2b, qf3w, qf3b, aw, ab);
    const size_t n4 = (size_t)B_SZ * CH * HW / 4;
    fuse_kernel<<<(unsigned)(n4 / 256), 256>>>((float*)d_out);
}

// round 4
// speedup vs baseline: 2.0682x; 1.3549x over previous
#include <cuda_runtime.h>
#include <math.h>
#include <stdint.h>

// Problem constants
#define B_SZ   4
#define L_SZ   5
#define NIMG   20          // B*L
#define CH     64
#define IMH    256
#define IMW    128
#define HW     (IMH*IMW)   // 32768

// ---------------- scratch (static device globals; no allocation) ----------------
__device__ float g_neigh[NIMG * CH * HW];          // (20,64,256,128)
__device__ float g_c1[NIMG * 32 * 128 * 64];       // (20,32,128,64)
__device__ float g_c2[NIMG * 64 * 64 * 32];        // (20,64,64,32)
__device__ float g_c3[NIMG * 64 * 32 * 16];        // (20,64,32,16)
__device__ float g_attn[B_SZ * L_SZ];              // (4,5)

// ---------------- helpers ----------------
__device__ __forceinline__ float tf32r(float v) {
    uint32_t u;
    asm("cvt.rna.tf32.f32 %0, %1;" : "=r"(u) : "f"(v));
    return __uint_as_float(u);
}

// ---------------- Kernel 1: affine grid + bilinear sample ----------------
__global__ void sample_kernel(const float* __restrict__ x, const float* __restrict__ nam)
{
    const int n  = blockIdx.y;
    const int yy = blockIdx.x;
    const int xx = threadIdx.x;
    const int b  = n / L_SZ, l = n % L_SZ;

    const float* th = nam + (b * 25 + l) * 6;
    const float t00 = th[0], t01 = th[1], t02 = th[2];
    const float t10 = th[3], t11 = th[4], t12 = th[5];

    const float gxn = (xx + 0.5f) * (2.0f / IMW) - 1.0f;
    const float gyn = (yy + 0.5f) * (2.0f / IMH) - 1.0f;
    const float gx = t00 * gxn + t01 * gyn + t02;
    const float gy = t10 * gxn + t11 * gyn + t12;
    const float sx = ((gx + 1.0f) * IMW - 1.0f) * 0.5f;
    const float sy = ((gy + 1.0f) * IMH - 1.0f) * 0.5f;

    const float x0f = floorf(sx), y0f = floorf(sy);
    const float fx = sx - x0f, fy = sy - y0f;
    const int x0 = (int)x0f, y0 = (int)y0f;

    const int   xs[2] = { x0, x0 + 1 };
    const int   ys[2] = { y0, y0 + 1 };
    const float wx[2] = { 1.0f - fx, fx };
    const float wy[2] = { 1.0f - fy, fy };

    int   off[4];
    float wv[4];
    int k = 0;
    #pragma unroll
    for (int jy = 0; jy < 2; jy++)
        #pragma unroll
        for (int jx = 0; jx < 2; jx++, k++) {
            const int ix = xs[jx], iy = ys[jy];
            const bool v = (ix >= 0) && (ix < IMW) && (iy >= 0) && (iy < IMH);
            const int icx = min(max(ix, 0), IMW - 1);
            const int icy = min(max(iy, 0), IMH - 1);
            off[k] = icy * IMW + icx;
            wv[k]  = v ? wx[jx] * wy[jy] : 0.0f;
        }

    const float* img = x + (size_t)n * CH * HW;
    float* dst = g_neigh + (size_t)n * CH * HW + yy * IMW + xx;
    #pragma unroll 4
    for (int c = 0; c < CH; c++) {
        const float* ic = img + (size_t)c * HW;
        const float v = wv[0] * ic[off[0]] + wv[1] * ic[off[1]]
                      + wv[2] * ic[off[2]] + wv[3] * ic[off[3]];
        dst[(size_t)c * HW] = v;
    }
}

// ---------------- tf32 tensor-core implicit-GEMM 4x4 s2 p1 conv + bias + relu ----------------
// M tile = 128 spatial positions (ROWS output rows x OW cols), N tile = COUTB couts,
// K = CIN*16 taps. 8 warps; warp strip = 16 consecutive ox of one output row (m16).
// Input window + weights staged in smem (tf32-rounded), channel granule padded to 9
// floats for conflict-free fragment LDS. A-fragment reused across all n8 tiles.
template<int CIN, int COUT, int IH, int IW, int COUTB>
__global__ __launch_bounds__(256)
void conv_mma(const float* __restrict__ in, const float* __restrict__ wgt,
              const float* __restrict__ bias, float* __restrict__ out)
{
    constexpr int OH   = IH / 2, OW = IW / 2;
    constexpr int ROWS = 128 / OW;              // output rows per block
    constexpr int INR  = 2 * ROWS + 2;          // input rows in window
    constexpr int WP   = IW + 2;                // cols incl 1 pad each side
    constexpr int CIP  = 9;                     // padded channel granule (8 staged)
    constexpr int NT   = COUTB / 8;             // n8 tiles per warp
    constexpr int SPR  = OW / 16;               // warp strips per output row
    static_assert(ROWS * OW == 128 && 8 % SPR == 0, "tiling");

    __shared__ float s_win[INR][WP][CIP];
    __shared__ float s_w[16][COUTB][CIP];

    const int n     = blockIdx.y;
    const int oy0   = blockIdx.x * ROWS;
    const int cbase = blockIdx.z * COUTB;
    const int t     = threadIdx.x;
    const int warp  = t >> 5;
    const int lane  = t & 31;

    const int row_local = warp / SPR;           // 0..ROWS-1
    const int ox0       = (warp % SPR) * 16;
    const int qid       = lane >> 2;            // 0..7
    const int ci0       = lane & 3;

    float acc[NT][4];
    #pragma unroll
    for (int j = 0; j < NT; j++)
        #pragma unroll
        for (int p = 0; p < 4; p++) acc[j][p] = 0.0f;

    const float* inN = in + (size_t)n * CIN * IH * IW;
    const int y0 = 2 * oy0 - 1;

    for (int cb = 0; cb < CIN; cb += 8) {
        __syncthreads();
        // stage input window (8 cins), zero-padded, tf32-rounded, cin-last layout
        for (int idx = t; idx < 8 * INR * WP; idx += 256) {
            const int ci  = idx / (INR * WP);
            const int rem = idx % (INR * WP);
            const int rr  = rem / WP, col = rem % WP;
            const int iy = y0 + rr, ix = col - 1;
            float v = 0.0f;
            if (iy >= 0 && iy < IH && ix >= 0 && ix < IW)
                v = inN[(size_t)(cb + ci) * IH * IW + (size_t)iy * IW + ix];
            s_win[rr][col][ci] = tf32r(v);
        }
        // stage weights: s_w[tap][o][ci], tf32-rounded
        for (int idx = t; idx < 16 * COUTB * 8; idx += 256) {
            const int o   = idx / 128;
            const int rem = idx % 128;
            const int ci  = rem / 16, tap = rem % 16;
            const float v = wgt[(size_t)(cbase + o) * CIN * 16 + (size_t)(cb + ci) * 16 + tap];
            s_w[tap][o][ci] = tf32r(v);
        }
        __syncthreads();

        #pragma unroll 4
        for (int tap = 0; tap < 16; tap++) {
            const int ky = tap >> 2, kx = tap & 3;
            const int iyl = 2 * row_local + ky;
            const int ixp = 2 * (ox0 + qid) + kx;

            const uint32_t a0 = __float_as_uint(s_win[iyl][ixp][ci0]);
            const uint32_t a1 = __float_as_uint(s_win[iyl][ixp + 16][ci0]);
            const uint32_t a2 = __float_as_uint(s_win[iyl][ixp][ci0 + 4]);
            const uint32_t a3 = __float_as_uint(s_win[iyl][ixp + 16][ci0 + 4]);

            #pragma unroll
            for (int j = 0; j < NT; j++) {
                const uint32_t b0 = __float_as_uint(s_w[tap][j * 8 + qid][ci0]);
                const uint32_t b1 = __float_as_uint(s_w[tap][j * 8 + qid][ci0 + 4]);
                asm volatile(
                    "mma.sync.aligned.m16n8k8.row.col.f32.tf32.tf32.f32 "
                    "{%0,%1,%2,%3}, {%4,%5,%6,%7}, {%8,%9}, {%0,%1,%2,%3};"
                    : "+f"(acc[j][0]), "+f"(acc[j][1]), "+f"(acc[j][2]), "+f"(acc[j][3])
                    : "r"(a0), "r"(a1), "r"(a2), "r"(a3), "r"(b0), "r"(b1));
            }
        }
    }

    // epilogue: bias + relu, scatter stores
    const int oy = oy0 + row_local;
    const int ox = ox0 + qid;
    #pragma unroll
    for (int j = 0; j < NT; j++) {
        const int c0 = cbase + j * 8 + ci0 * 2;
        const float bv0 = bias[c0], bv1 = bias[c0 + 1];
        float* o0 = out + (((size_t)n * COUT + c0) * OH + oy) * OW;
        float* o1 = out + (((size_t)n * COUT + c0 + 1) * OH + oy) * OW;
        o0[ox]     = fmaxf(acc[j][0] + bv0, 0.0f);
        o1[ox]     = fmaxf(acc[j][1] + bv1, 0.0f);
        o0[ox + 8] = fmaxf(acc[j][2] + bv0, 0.0f);
        o1[ox + 8] = fmaxf(acc[j][3] + bv1, 0.0f);
    }
}

// ---------------- Kernel 5: pool + key/query MLPs + attention softmax ----------------
__global__ void attn_kernel(const float* __restrict__ kf1w, const float* __restrict__ kf1b,
                            const float* __restrict__ kf2w, const float* __restrict__ kf2b,
                            const float* __restrict__ kf3w, const float* __restrict__ kf3b,
                            const float* __restrict__ qf1w, const float* __restrict__ qf1b,
                            const float* __restrict__ qf2w, const float* __restrict__ qf2b,
                            const float* __restrict__ qf3w, const float* __restrict__ qf3b,
                            const float* __restrict__ aw,   const float* __restrict__ ab)
{
    const int b = blockIdx.x;
    const int t = threadIdx.x;

    __shared__ float pooled[L_SZ][64];
    __shared__ float h1[L_SZ][256];
    __shared__ float h2[L_SZ][128];
    __shared__ float keys[L_SZ][256];
    __shared__ float q1[256], q2[128], qv[32], qq[256];
    __shared__ float logit[L_SZ];

    for (int idx = t; idx < L_SZ * 64; idx += 256) {
        const int l = idx / 64, c = idx % 64;
        const float4* p = (const float4*)(g_c3 + ((size_t)(b * L_SZ + l) * 64 + c) * 512);
        float s = 0.0f;
        #pragma unroll 4
        for (int i = 0; i < 128; i++) {
            const float4 v = p[i];
            s += (v.x + v.y) + (v.z + v.w);
        }
        pooled[l][c] = s * (1.0f / 512.0f);
    }
    __syncthreads();

    for (int idx = t; idx < L_SZ * 256; idx += 256) {
        const int l = idx / 256, o = idx % 256;
        float s = kf1b[o];
        for (int i = 0; i < 64; i++) s = fmaf(pooled[l][i], kf1w[o * 64 + i], s);
        h1[l][o] = fmaxf(s, 0.0f);
    }
    __syncthreads();
    for (int idx = t; idx < L_SZ * 128; idx += 256) {
        const int l = idx / 128, o = idx % 128;
        float s = kf2b[o];
        for (int i = 0; i < 256; i++) s = fmaf(h1[l][i], kf2w[o * 256 + i], s);
        h2[l][o] = fmaxf(s, 0.0f);
    }
    __syncthreads();
    for (int idx = t; idx < L_SZ * 256; idx += 256) {
        const int l = idx / 256, o = idx % 256;
        float s = kf3b[o];
        for (int i = 0; i < 128; i++) s = fmaf(h2[l][i], kf3w[o * 128 + i], s);
        keys[l][o] = s;
    }
    __syncthreads();

    {
        float s = qf1b[t];
        for (int i = 0; i < 64; i++) s = fmaf(pooled[0][i], qf1w[t * 64 + i], s);
        q1[t] = fmaxf(s, 0.0f);
    }
    __syncthreads();
    if (t < 128) {
        float s = qf2b[t];
        for (int i = 0; i < 256; i++) s = fmaf(q1[i], qf2w[t * 256 + i], s);
        q2[t] = fmaxf(s, 0.0f);
    }
    __syncthreads();
    if (t < 32) {
        float s = qf3b[t];
        for (int i = 0; i < 128; i++) s = fmaf(q2[i], qf3w[t * 128 + i], s);
        qv[t] = s;
    }
    __syncthreads();
    {
        float s = ab[t];
        for (int i = 0; i < 32; i++) s = fmaf(qv[i], aw[t * 32 + i], s);
        qq[t] = s;
    }
    __syncthreads();
    if (t < L_SZ) {
        float s = 0.0f;
        for (int i = 0; i < 256; i++) s = fmaf(keys[t][i], qq[i], s);
        logit[t] = s;
    }
    __syncthreads();
    if (t == 0) {
        float m = logit[0];
        for (int l = 1; l < L_SZ; l++) m = fmaxf(m, logit[l]);
        float e[L_SZ], ssum = 0.0f;
        for (int l = 0; l < L_SZ; l++) { e[l] = expf(logit[l] - m); ssum += e[l]; }
        const float inv = 1.0f / ssum;
        for (int l = 0; l < L_SZ; l++) g_attn[b * L_SZ + l] = e[l] * inv;
    }
}

// ---------------- Kernel 6: attention-weighted sum of neigh ----------------
__global__ void fuse_kernel(float* __restrict__ out)
{
    const size_t i = (size_t)blockIdx.x * blockDim.x + threadIdx.x;
    const size_t per_b = (size_t)CH * HW / 4;
    const int b = (int)(i / per_b);
    const size_t rem = i % per_b;

    float a[L_SZ];
    #pragma unroll
    for (int l = 0; l < L_SZ; l++) a[l] = g_attn[b * L_SZ + l];

    const float4* nv = (const float4*)g_neigh;
    float4 s = make_float4(0.f, 0.f, 0.f, 0.f);
    #pragma unroll
    for (int l = 0; l < L_SZ; l++) {
        const float4 v = nv[(size_t)(b * L_SZ + l) * per_b + rem];
        s.x = fmaf(a[l], v.x, s.x);
        s.y = fmaf(a[l], v.y, s.y);
        s.z = fmaf(a[l], v.z, s.z);
        s.w = fmaf(a[l], v.w, s.w);
    }
    ((float4*)out)[i] = s;
}

// ---------------- launch ----------------
extern "C" void kernel_launch(void* const* d_in, const int* in_sizes, int n_in,
                              void* d_out, int out_size)
{
    const float* x    = (const float*)d_in[0];
    const float* nam  = (const float*)d_in[2];
    const float* w1   = (const float*)d_in[3];
    const float* b1   = (const float*)d_in[4];
    const float* w2   = (const float*)d_in[5];
    const float* b2   = (const float*)d_in[6];
    const float* w3   = (const float*)d_in[7];
    const float* b3   = (const float*)d_in[8];
    const float* kf1w = (const float*)d_in[9];
    const float* kf1b = (const float*)d_in[10];
    const float* kf2w = (const float*)d_in[11];
    const float* kf2b = (const float*)d_in[12];
    const float* kf3w = (const float*)d_in[13];
    const float* kf3b = (const float*)d_in[14];
    const float* qf1w = (const float*)d_in[15];
    const float* qf1b = (const float*)d_in[16];
    const float* qf2w = (const float*)d_in[17];
    const float* qf2b = (const float*)d_in[18];
    const float* qf3w = (const float*)d_in[19];
    const float* qf3b = (const float*)d_in[20];
    const float* aw   = (const float*)d_in[21];
    const float* ab   = (const float*)d_in[22];

    float *p_neigh, *p_c1, *p_c2, *p_c3;
    cudaGetSymbolAddress((void**)&p_neigh, g_neigh);
    cudaGetSymbolAddress((void**)&p_c1, g_c1);
    cudaGetSymbolAddress((void**)&p_c2, g_c2);
    cudaGetSymbolAddress((void**)&p_c3, g_c3);

    sample_kernel<<<dim3(IMH, NIMG), IMW>>>(x, nam);

    // conv1: 64->32 @256x128. grid (OH/ROWS=64, 20, 1)
    conv_mma<64, 32, 256, 128, 32><<<dim3(64, NIMG, 1), 256>>>(p_neigh, w1, b1, p_c1);
    // conv2: 32->64 @128x64. grid (16, 20, 2)
    conv_mma<32, 64, 128, 64, 32><<<dim3(16, NIMG, 2), 256>>>(p_c1, w2, b2, p_c2);
    // conv3: 64->64 @64x32. grid (4, 20, 2)
    conv_mma<64, 64, 64, 32, 32><<<dim3(4, NIMG, 2), 256>>>(p_c2, w3, b3, p_c3);

    attn_kernel<<<B_SZ, 256>>>(kf1w, kf1b, kf2w, kf2b, kf3w, kf3b,
                               qf1w, qf1b, qf2w, qf2b, qf3w, qf3b, aw, ab);
    const size_t n4 = (size_t)B_SZ * CH * HW / 4;
    fuse_kernel<<<(unsigned)(n4 / 256), 256>>>((float*)d_out);
}

// round 5
// speedup vs baseline: 2.6801x; 1.2958x over previous
#include <cuda_runtime.h>
#include <math.h>
#include <stdint.h>

// Problem constants
#define B_SZ   4
#define L_SZ   5
#define NIMG   20          // B*L
#define CH     64
#define IMH    256
#define IMW    128
#define HW     (IMH*IMW)   // 32768

// ---------------- scratch (static device globals; no allocation) ----------------
__device__ float g_neigh[NIMG * CH * HW];          // (20,64,256,128)
__device__ float g_c1[NIMG * 32 * 128 * 64];       // (20,32,128,64)
__device__ float g_c2[NIMG * 64 * 64 * 32];        // (20,64,64,32)
__device__ float g_c3[NIMG * 64 * 32 * 16];        // (20,64,32,16)
__device__ float g_pool[NIMG * 64];                // pooled features
__device__ float g_attn[B_SZ * L_SZ];              // (4,5)

// ---------------- helpers ----------------
__device__ __forceinline__ float tf32r(float v) {
    uint32_t u;
    asm("cvt.rna.tf32.f32 %0, %1;" : "=r"(u) : "f"(v));
    return __uint_as_float(u);
}

// ---------------- Kernel 1: affine grid + bilinear sample ----------------
__global__ void sample_kernel(const float* __restrict__ x, const float* __restrict__ nam)
{
    const int n  = blockIdx.y;
    const int yy = blockIdx.x;
    const int xx = threadIdx.x;
    const int b  = n / L_SZ, l = n % L_SZ;

    const float* th = nam + (b * 25 + l) * 6;
    const float t00 = th[0], t01 = th[1], t02 = th[2];
    const float t10 = th[3], t11 = th[4], t12 = th[5];

    const float gxn = (xx + 0.5f) * (2.0f / IMW) - 1.0f;
    const float gyn = (yy + 0.5f) * (2.0f / IMH) - 1.0f;
    const float gx = t00 * gxn + t01 * gyn + t02;
    const float gy = t10 * gxn + t11 * gyn + t12;
    const float sx = ((gx + 1.0f) * IMW - 1.0f) * 0.5f;
    const float sy = ((gy + 1.0f) * IMH - 1.0f) * 0.5f;

    const float x0f = floorf(sx), y0f = floorf(sy);
    const float fx = sx - x0f, fy = sy - y0f;
    const int x0 = (int)x0f, y0 = (int)y0f;

    const int   xs[2] = { x0, x0 + 1 };
    const int   ys[2] = { y0, y0 + 1 };
    const float wx[2] = { 1.0f - fx, fx };
    const float wy[2] = { 1.0f - fy, fy };

    int   off[4];
    float wv[4];
    int k = 0;
    #pragma unroll
    for (int jy = 0; jy < 2; jy++)
        #pragma unroll
        for (int jx = 0; jx < 2; jx++, k++) {
            const int ix = xs[jx], iy = ys[jy];
            const bool v = (ix >= 0) && (ix < IMW) && (iy >= 0) && (iy < IMH);
            const int icx = min(max(ix, 0), IMW - 1);
            const int icy = min(max(iy, 0), IMH - 1);
            off[k] = icy * IMW + icx;
            wv[k]  = v ? wx[jx] * wy[jy] : 0.0f;
        }

    const float* img = x + (size_t)n * CH * HW;
    float* dst = g_neigh + (size_t)n * CH * HW + yy * IMW + xx;
    #pragma unroll 4
    for (int c = 0; c < CH; c++) {
        const float* ic = img + (size_t)c * HW;
        const float v = wv[0] * ic[off[0]] + wv[1] * ic[off[1]]
                      + wv[2] * ic[off[2]] + wv[3] * ic[off[3]];
        dst[(size_t)c * HW] = v;
    }
}

// ---------------- tf32 tensor-core conv, pipelined v2 ----------------
// Block: 8 warps, M tile = 128 positions (ROWS rows x OW cols), N tile = COUTB.
// K chunk = 8 cins x 16 taps. Software pipeline: chunk k+1 global->regs while
// MMA runs on chunk k in smem. Paired-ci interleave (k,k+4 adjacent) so A/B
// fragments load as float2; pitches chosen conflict-free (2*20=40=8 mod 32,
// 296=8 mod 32).
template<int CIN, int COUT, int IH, int IW, int COUTB>
__global__ __launch_bounds__(256, 2)
void conv_mma2(const float* __restrict__ in, const float* __restrict__ wgt,
               const float* __restrict__ bias, float* __restrict__ out)
{
    constexpr int OH   = IH / 2, OW = IW / 2;
    constexpr int ROWS = 128 / OW;
    constexpr int INR  = 2 * ROWS + 2;
    constexpr int WP   = IW + 2;
    constexpr int CIP  = 20;                 // ci-pair pitch: 16 data + 4 pad
    constexpr int WTP  = 18;                 // per-tap weight pitch
    constexpr int POW  = 16 * WTP + 8;       // per-cout pitch = 296 (=8 mod 32)
    constexpr int NT   = COUTB / 8;
    constexpr int SPR  = OW / 16;
    constexpr int SIN  = 8 * INR * WP;
    constexpr int NI   = (SIN + 255) / 256;
    constexpr int NW   = (16 * COUTB * 8) / 256;
    static_assert(ROWS * OW == 128 && 8 % SPR == 0 && NW * 256 == 16 * COUTB * 8, "tiling");

    extern __shared__ float sm[];
    float* s_win = sm;                       // [INR][WP][CIP]
    float* s_w   = sm + INR * WP * CIP;      // [COUTB][16][WTP] (POW per cout)

    const int n     = blockIdx.y;
    const int oy0   = blockIdx.x * ROWS;
    const int cbase = blockIdx.z * COUTB;
    const int t     = threadIdx.x;
    const int warp  = t >> 5;
    const int lane  = t & 31;

    const int row_local = warp / SPR;
    const int ox0       = (warp % SPR) * 16;
    const int qid       = lane >> 2;
    const int ci0       = lane & 3;

    float acc[NT][4];
    #pragma unroll
    for (int j = 0; j < NT; j++)
        #pragma unroll
        for (int p = 0; p < 4; p++) acc[j][p] = 0.0f;

    const float* inN = in + (size_t)n * CIN * IH * IW;
    const int y0 = 2 * oy0 - 1;

    float rin[NI];
    float rw[NW];

    // load chunk cb (8 cins) into registers
    auto LOAD = [&](int cb) {
        #pragma unroll
        for (int i = 0; i < NI; i++) {
            const int idx = t + i * 256;
            float v = 0.0f;
            if (idx < SIN) {
                const int ci  = idx / (INR * WP);
                const int rem = idx % (INR * WP);
                const int rr  = rem / WP, col = rem % WP;
                const int iy = y0 + rr, ix = col - 1;
                if (iy >= 0 && iy < IH && (unsigned)ix < (unsigned)IW)
                    v = inN[(size_t)(cb + ci) * IH * IW + (size_t)iy * IW + ix];
            }
            rin[i] = v;
        }
        #pragma unroll
        for (int i = 0; i < NW; i++) {
            const int idx = t + i * 256;
            const int o = idx >> 7, rem = idx & 127;
            const int ci = rem >> 4, tap = rem & 15;
            rw[i] = wgt[(size_t)(cbase + o) * CIN * 16 + (size_t)(cb + ci) * 16 + tap];
        }
    };
    // registers -> smem (tf32 rounded, paired-ci interleave)
    auto STORE = [&]() {
        #pragma unroll
        for (int i = 0; i < NI; i++) {
            const int idx = t + i * 256;
            if (idx < SIN) {
                const int ci  = idx / (INR * WP);
                const int rem = idx % (INR * WP);
                const int rr  = rem / WP, col = rem % WP;
                const int pc  = ((ci & 3) << 1) | (ci >> 2);
                s_win[(rr * WP + col) * CIP + pc] = tf32r(rin[i]);
            }
        }
        #pragma unroll
        for (int i = 0; i < NW; i++) {
            const int idx = t + i * 256;
            const int o = idx >> 7, rem = idx & 127;
            const int ci = rem >> 4, tap = rem & 15;
            const int pc = ((ci & 3) << 1) | (ci >> 2);
            s_w[o * POW + tap * WTP + pc] = tf32r(rw[i]);
        }
    };

    LOAD(0);
    STORE();
    __syncthreads();

    for (int cb = 0; cb < CIN; cb += 8) {
        const bool more = (cb + 8 < CIN);
        if (more) LOAD(cb + 8);              // in flight during MMA below

        #pragma unroll
        for (int ky = 0; ky < 4; ky++) {
            const float* rowp = &s_win[(((2 * row_local + ky) * WP) + 2 * (ox0 + qid)) * CIP + 2 * ci0];
            #pragma unroll
            for (int kx = 0; kx < 4; kx++) {
                const float2 A0 = *(const float2*)(rowp + kx * CIP);          // rows qid:   k=ci0, ci0+4
                const float2 A1 = *(const float2*)(rowp + (kx + 16) * CIP);   // rows qid+8
                const int tap = ky * 4 + kx;
                #pragma unroll
                for (int j = 0; j < NT; j++) {
                    const float2 Bv = *(const float2*)&s_w[(j * 8 + qid) * POW + tap * WTP + 2 * ci0];
                    asm volatile(
                        "mma.sync.aligned.m16n8k8.row.col.f32.tf32.tf32.f32 "
                        "{%0,%1,%2,%3}, {%4,%5,%6,%7}, {%8,%9}, {%0,%1,%2,%3};"
                        : "+f"(acc[j][0]), "+f"(acc[j][1]), "+f"(acc[j][2]), "+f"(acc[j][3])
                        : "r"(__float_as_uint(A0.x)), "r"(__float_as_uint(A1.x)),
                          "r"(__float_as_uint(A0.y)), "r"(__float_as_uint(A1.y)),
                          "r"(__float_as_uint(Bv.x)), "r"(__float_as_uint(Bv.y)));
                }
            }
        }
        __syncthreads();
        if (more) { STORE(); __syncthreads(); }
    }

    // epilogue: bias + relu
    const int oy = oy0 + row_local;
    const int ox = ox0 + qid;
    #pragma unroll
    for (int j = 0; j < NT; j++) {
        const int c0 = cbase + j * 8 + ci0 * 2;
        const float bv0 = bias[c0], bv1 = bias[c0 + 1];
        float* o0 = out + (((size_t)n * COUT + c0) * OH + oy) * OW;
        float* o1 = out + (((size_t)n * COUT + c0 + 1) * OH + oy) * OW;
        o0[ox]     = fmaxf(acc[j][0] + bv0, 0.0f);
        o1[ox]     = fmaxf(acc[j][1] + bv1, 0.0f);
        o0[ox + 8] = fmaxf(acc[j][2] + bv0, 0.0f);
        o1[ox + 8] = fmaxf(acc[j][3] + bv1, 0.0f);
    }
}

// ---------------- mean pool: one warp per (n, c) reduction over 512 ----------------
__global__ void pool_kernel()
{
    const int gw   = (blockIdx.x * blockDim.x + threadIdx.x) >> 5;   // 0..1279
    const int lane = threadIdx.x & 31;
    const float4* p = (const float4*)(g_c3 + (size_t)gw * 512);
    float s = 0.0f;
    #pragma unroll
    for (int i = lane; i < 128; i += 32) {
        const float4 v = p[i];
        s += (v.x + v.y) + (v.z + v.w);
    }
    #pragma unroll
    for (int o = 16; o; o >>= 1) s += __shfl_xor_sync(0xffffffffu, s, o);
    if (lane == 0) g_pool[gw] = s * (1.0f / 512.0f);
}

// ---------------- attention: MLPs + softmax ----------------
__global__ void attn_kernel(const float* __restrict__ kf1w, const float* __restrict__ kf1b,
                            const float* __restrict__ kf2w, const float* __restrict__ kf2b,
                            const float* __restrict__ kf3w, const float* __restrict__ kf3b,
                            const float* __restrict__ qf1w, const float* __restrict__ qf1b,
                            const float* __restrict__ qf2w, const float* __restrict__ qf2b,
                            const float* __restrict__ qf3w, const float* __restrict__ qf3b,
                            const float* __restrict__ aw,   const float* __restrict__ ab)
{
    const int b = blockIdx.x;
    const int t = threadIdx.x;

    __shared__ float pooled[L_SZ][64];
    __shared__ float h1[L_SZ][256];
    __shared__ float h2[L_SZ][128];
    __shared__ float keys[L_SZ][256];
    __shared__ float q1[256], q2[128], qv[32], qq[256];
    __shared__ float logit[L_SZ];

    for (int idx = t; idx < L_SZ * 64; idx += 256) {
        const int l = idx / 64, c = idx % 64;
        pooled[l][c] = g_pool[(b * L_SZ + l) * 64 + c];
    }
    __syncthreads();

    for (int idx = t; idx < L_SZ * 256; idx += 256) {
        const int l = idx / 256, o = idx % 256;
        float s = kf1b[o];
        for (int i = 0; i < 64; i++) s = fmaf(pooled[l][i], kf1w[o * 64 + i], s);
        h1[l][o] = fmaxf(s, 0.0f);
    }
    __syncthreads();
    for (int idx = t; idx < L_SZ * 128; idx += 256) {
        const int l = idx / 128, o = idx % 128;
        float s = kf2b[o];
        for (int i = 0; i < 256; i++) s = fmaf(h1[l][i], kf2w[o * 256 + i], s);
        h2[l][o] = fmaxf(s, 0.0f);
    }
    __syncthreads();
    for (int idx = t; idx < L_SZ * 256; idx += 256) {
        const int l = idx / 256, o = idx % 256;
        float s = kf3b[o];
        for (int i = 0; i < 128; i++) s = fmaf(h2[l][i], kf3w[o * 128 + i], s);
        keys[l][o] = s;
    }
    __syncthreads();

    {
        float s = qf1b[t];
        for (int i = 0; i < 64; i++) s = fmaf(pooled[0][i], qf1w[t * 64 + i], s);
        q1[t] = fmaxf(s, 0.0f);
    }
    __syncthreads();
    if (t < 128) {
        float s = qf2b[t];
        for (int i = 0; i < 256; i++) s = fmaf(q1[i], qf2w[t * 256 + i], s);
        q2[t] = fmaxf(s, 0.0f);
    }
    __syncthreads();
    if (t < 32) {
        float s = qf3b[t];
        for (int i = 0; i < 128; i++) s = fmaf(q2[i], qf3w[t * 128 + i], s);
        qv[t] = s;
    }
    __syncthreads();
    {
        float s = ab[t];
        for (int i = 0; i < 32; i++) s = fmaf(qv[i], aw[t * 32 + i], s);
        qq[t] = s;
    }
    __syncthreads();
    if (t < L_SZ) {
        float s = 0.0f;
        for (int i = 0; i < 256; i++) s = fmaf(keys[t][i], qq[i], s);
        logit[t] = s;
    }
    __syncthreads();
    if (t == 0) {
        float m = logit[0];
        for (int l = 1; l < L_SZ; l++) m = fmaxf(m, logit[l]);
        float e[L_SZ], ssum = 0.0f;
        for (int l = 0; l < L_SZ; l++) { e[l] = expf(logit[l] - m); ssum += e[l]; }
        const float inv = 1.0f / ssum;
        for (int l = 0; l < L_SZ; l++) g_attn[b * L_SZ + l] = e[l] * inv;
    }
}

// ---------------- attention-weighted sum of neigh ----------------
__global__ void fuse_kernel(float* __restrict__ out)
{
    const size_t i = (size_t)blockIdx.x * blockDim.x + threadIdx.x;
    const size_t per_b = (size_t)CH * HW / 4;
    const int b = (int)(i / per_b);
    const size_t rem = i % per_b;

    float a[L_SZ];
    #pragma unroll
    for (int l = 0; l < L_SZ; l++) a[l] = g_attn[b * L_SZ + l];

    const float4* nv = (const float4*)g_neigh;
    float4 s = make_float4(0.f, 0.f, 0.f, 0.f);
    #pragma unroll
    for (int l = 0; l < L_SZ; l++) {
        const float4 v = nv[(size_t)(b * L_SZ + l) * per_b + rem];
        s.x = fmaf(a[l], v.x, s.x);
        s.y = fmaf(a[l], v.y, s.y);
        s.z = fmaf(a[l], v.z, s.z);
        s.w = fmaf(a[l], v.w, s.w);
    }
    ((float4*)out)[i] = s;
}

// ---------------- launch ----------------
extern "C" void kernel_launch(void* const* d_in, const int* in_sizes, int n_in,
                              void* d_out, int out_size)
{
    const float* x    = (const float*)d_in[0];
    const float* nam  = (const float*)d_in[2];
    const float* w1   = (const float*)d_in[3];
    const float* b1   = (const float*)d_in[4];
    const float* w2   = (const float*)d_in[5];
    const float* b2   = (const float*)d_in[6];
    const float* w3   = (const float*)d_in[7];
    const float* b3   = (const float*)d_in[8];
    const float* kf1w = (const float*)d_in[9];
    const float* kf1b = (const float*)d_in[10];
    const float* kf2w = (const float*)d_in[11];
    const float* kf2b = (const float*)d_in[12];
    const float* kf3w = (const float*)d_in[13];
    const float* kf3b = (const float*)d_in[14];
    const float* qf1w = (const float*)d_in[15];
    const float* qf1b = (const float*)d_in[16];
    const float* qf2w = (const float*)d_in[17];
    const float* qf2b = (const float*)d_in[18];
    const float* qf3w = (const float*)d_in[19];
    const float* qf3b = (const float*)d_in[20];
    const float* aw   = (const float*)d_in[21];
    const float* ab   = (const float*)d_in[22];

    float *p_neigh, *p_c1, *p_c2, *p_c3;
    cudaGetSymbolAddress((void**)&p_neigh, g_neigh);
    cudaGetSymbolAddress((void**)&p_c1, g_c1);
    cudaGetSymbolAddress((void**)&p_c2, g_c2);
    cudaGetSymbolAddress((void**)&p_c3, g_c3);

    // dynamic smem sizes (bytes)
    constexpr int SM1 = (6 * 130 * 20 + 32 * 296) * 4;   // 100,288
    constexpr int SM2 = (10 * 66 * 20 + 32 * 296) * 4;   //  90,688
    constexpr int SM3 = (18 * 34 * 20 + 16 * 296) * 4;   //  67,904

    cudaFuncSetAttribute((const void*)conv_mma2<64, 32, 256, 128, 32>,
                         cudaFuncAttributeMaxDynamicSharedMemorySize, SM1);
    cudaFuncSetAttribute((const void*)conv_mma2<32, 64, 128, 64, 32>,
                         cudaFuncAttributeMaxDynamicSharedMemorySize, SM2);
    cudaFuncSetAttribute((const void*)conv_mma2<64, 64, 64, 32, 16>,
                         cudaFuncAttributeMaxDynamicSharedMemorySize, SM3);

    sample_kernel<<<dim3(IMH, NIMG), IMW>>>(x, nam);

    conv_mma2<64, 32, 256, 128, 32><<<dim3(64, NIMG, 1), 256, SM1>>>(p_neigh, w1, b1, p_c1);
    conv_mma2<32, 64, 128, 64, 32><<<dim3(16, NIMG, 2), 256, SM2>>>(p_c1, w2, b2, p_c2);
    conv_mma2<64, 64, 64, 32, 16><<<dim3(4, NIMG, 4), 256, SM3>>>(p_c2, w3, b3, p_c3);

    pool_kernel<<<160, 256>>>();
    attn_kernel<<<B_SZ, 256>>>(kf1w, kf1b, kf2w, kf2b, kf3w, kf3b,
                               qf1w, qf1b, qf2w, qf2b, qf3w, qf3b, aw, ab);
    const size_t n4 = (size_t)B_SZ * CH * HW / 4;
    fuse_kernel<<<(unsigned)(n4 / 256), 256>>>((float*)d_out);
}